// round 8
// baseline (speedup 1.0000x reference)
#include <cuda_runtime.h>
#include <cuda_bf16.h>

// SelfBallPointQuery: B=16, C=3, N=2048, RADIUS=0.2, MAX_SAMPLES=64
// Output float32 (B, N, 64): first 64 ascending in-radius indices, padded with
// the first index. R7 passed (rel_err 0) with this dtype/layout.
//
// R8: branchless inner loop. The R7 profile showed occ=10.4%, issue=32.4% —
// latency-bound on divergent-branch scaffolding (66% of iterations have >=1
// hitting lane -> BSSY/BSYNC). Replace the conditional emission with an
// unconditional STG whose target is SEL-selected between the real slot and a
// device sink. first-tracking removed (row[0] is always written: self always
// hits); padding reads it back.

#define BQ_B 16
#define BQ_N 2048
#define BQ_R2 0.04f
#define BQ_MS 64
#define BQ_THREADS 128
#define BQ_TILES (BQ_N / BQ_THREADS)   // 16 tiles per batch

__device__ float bq_sink[32];          // garbage absorber for non-hit stores

__global__ __launch_bounds__(BQ_THREADS)
void SelfBallPointQuery_56736517980692_kernel(const float* __restrict__ pcs,
                                              float* __restrict__ out) {
    __shared__ float4 pts[BQ_N];   // 32 KB: whole batch's point cloud

    const int b    = blockIdx.x >> 4;
    const int tile = blockIdx.x & (BQ_TILES - 1);

    // pcs layout: [b][c][n] -> x at +0, y at +N, z at +2N
    const float* base = pcs + (size_t)b * 3 * BQ_N;
    for (int n = threadIdx.x; n < BQ_N; n += BQ_THREADS) {
        pts[n] = make_float4(base[n], base[BQ_N + n], base[2 * BQ_N + n], 0.0f);
    }
    __syncthreads();

    const int i = tile * BQ_THREADS + threadIdx.x;  // this thread's query point
    const float4 q = pts[i];
    const float qx = q.x, qy = q.y, qz = q.z;

    float* row  = out + (size_t)(b * BQ_N + i) * BQ_MS;
    float* sink = &bq_sink[threadIdx.x & 31];

    int   off = 0;      // = min(#hits so far, 64); also next store slot
    float jf  = 0.0f;   // float(j), exact (j < 2^24)

#pragma unroll 8
    for (int j = 0; j < BQ_N; ++j) {
        const float4 p = pts[j];               // LDS.128, warp-uniform broadcast
        const float dx = qx - p.x;
        const float dy = qy - p.y;
        const float dz = qz - p.z;
        float acc = __fmul_rn(dx, dx);
        acc = __fmaf_rn(dy, dy, acc);
        acc = __fmaf_rn(dz, dz, acc);

        const bool store = (acc < BQ_R2) & (off < BQ_MS);
        float* dst = store ? (row + off) : sink;   // SEL, no branch
        *dst = jf;                                 // unconditional STG
        off += (int)store;
        jf  += 1.0f;
    }

    // Pad [off, 64) with the first in-radius index. Self always hits, so
    // row[0] is always valid and off >= 1.
    const float f = row[0];
    for (int k = off; k < BQ_MS; ++k) {
        row[k] = f;
    }
}

extern "C" void kernel_launch(void* const* d_in, const int* in_sizes, int n_in,
                              void* d_out, int out_size) {
    (void)in_sizes; (void)n_in; (void)out_size;
    const float* pcs = (const float*)d_in[0];
    float*       out = (float*)d_out;
    dim3 grid(BQ_B * BQ_TILES);   // 256 blocks
    dim3 block(BQ_THREADS);       // 128 threads
    SelfBallPointQuery_56736517980692_kernel<<<grid, block>>>(pcs, out);
}

// round 9
// speedup vs baseline: 2.9620x; 2.9620x over previous
#include <cuda_runtime.h>
#include <cuda_bf16.h>

// SelfBallPointQuery: B=16, C=3, N=2048, RADIUS=0.2, MAX_SAMPLES=64
// Output float32 (B, N, 64): first 64 ascending in-radius indices, padded
// with the first in-radius index.
//
// R9: warp-per-query ballot compaction. R7 (93us) was latency-bound at
// occ=10% (1024 warps total); R8's sink-store fix regressed to 215us by
// trading branches for 67M contended global stores. This version scans j
// 32-wide per warp (8192 warps total), compacting hits with ballot+popc.

#define BQ_B 16
#define BQ_N 2048
#define BQ_R2 0.04f
#define BQ_MS 64
#define BQ_Q 4                         // queries per warp
#define BQ_WPB 4                       // warps per block
#define BQ_THREADS (BQ_WPB * 32)      // 128
#define BQ_QPB (BQ_WPB * BQ_Q)        // 16 queries per block
#define BQ_BLKS_PER_BATCH (BQ_N / BQ_QPB)  // 128

__global__ __launch_bounds__(BQ_THREADS)
void SelfBallPointQuery_56736517980692_kernel(const float* __restrict__ pcs,
                                              float* __restrict__ out) {
    __shared__ float4 pts[BQ_N];   // 32 KB

    const int b   = blockIdx.x >> 7;          // / BQ_BLKS_PER_BATCH
    const int blk = blockIdx.x & (BQ_BLKS_PER_BATCH - 1);

    // pcs layout: [b][c][n] -> x at +0, y at +N, z at +2N
    const float* base = pcs + (size_t)b * 3 * BQ_N;
    for (int n = threadIdx.x; n < BQ_N; n += BQ_THREADS) {
        pts[n] = make_float4(base[n], base[BQ_N + n], base[2 * BQ_N + n], 0.0f);
    }
    __syncthreads();

    const int warp = threadIdx.x >> 5;
    const int lane = threadIdx.x & 31;
    const unsigned below = (1u << lane) - 1u;

    const int i0 = blk * BQ_QPB + warp * BQ_Q;   // first of this warp's 4 queries

    float qx[BQ_Q], qy[BQ_Q], qz[BQ_Q];
    float* rows[BQ_Q];
    int cnt[BQ_Q];
    int first[BQ_Q];
#pragma unroll
    for (int q = 0; q < BQ_Q; ++q) {
        const float4 t = pts[i0 + q];
        qx[q] = t.x; qy[q] = t.y; qz[q] = t.z;
        rows[q] = out + (size_t)(b * BQ_N + i0 + q) * BQ_MS;
        cnt[q] = 0;
        first[q] = 0;
    }

    for (int jb = 0; jb < BQ_N; jb += 32) {
        const float4 p = pts[jb + lane];        // conflict-free LDS.128
        const float jf = (float)(jb + lane);

#pragma unroll
        for (int q = 0; q < BQ_Q; ++q) {
            const float dx = qx[q] - p.x;
            const float dy = qy[q] - p.y;
            const float dz = qz[q] - p.z;
            float acc = __fmul_rn(dx, dx);
            acc = __fmaf_rn(dy, dy, acc);
            acc = __fmaf_rn(dz, dz, acc);
            const bool hit = acc < BQ_R2;

            const unsigned m = __ballot_sync(0xffffffffu, hit);
            const int pos = cnt[q] + __popc(m & below);
            if (hit && pos < BQ_MS) rows[q][pos] = jf;   // rare predicated STG
            if (cnt[q] == 0 && m != 0u)                  // warp-uniform, rare
                first[q] = jb + __ffs(m) - 1;
            cnt[q] += __popc(m);
        }
    }

    // Lane-parallel padding with the first in-radius index.
#pragma unroll
    for (int q = 0; q < BQ_Q; ++q) {
        const int start = cnt[q] < BQ_MS ? cnt[q] : BQ_MS;
        const float f = (float)first[q];
        for (int k = start + lane; k < BQ_MS; k += 32) {
            rows[q][k] = f;
        }
    }
}

extern "C" void kernel_launch(void* const* d_in, const int* in_sizes, int n_in,
                              void* d_out, int out_size) {
    (void)in_sizes; (void)n_in; (void)out_size;
    const float* pcs = (const float*)d_in[0];
    float*       out = (float*)d_out;
    dim3 grid(BQ_B * BQ_BLKS_PER_BATCH);   // 2048 blocks
    dim3 block(BQ_THREADS);                // 128 threads
    SelfBallPointQuery_56736517980692_kernel<<<grid, block>>>(pcs, out);
}

// round 11
// speedup vs baseline: 4.3209x; 1.4588x over previous
#include <cuda_runtime.h>
#include <cuda_bf16.h>

// SelfBallPointQuery: B=16, C=3, N=2048, RADIUS=0.2, MAX_SAMPLES=64
// Output float32 (B, N, 64): first 64 ascending in-radius indices, padded
// with the first in-radius index.
//
// R11 = R9's EXACT distance math (subtract-then-square; benched rel_err 0.0;
// R10 proved the expanded |p|^2-2qp form flips ~4000 borderline pairs ->
// rel_err 1.9e-3 FAIL) + R10's structural wins:
//  * smem tiled 4 x 512 pts (8 KB) -> occupancy no longer smem-capped
//  * __launch_bounds__(128, 10): 40 warps/SM (~62% occ vs R9's 32.6%)
//  * no in-loop first-tracking: row slot 0 is always written (self always
//    hits at pos 0); padding reads it back after __syncwarp().

#define BQ_B 16
#define BQ_N 2048
#define BQ_MS 64
#define BQ_Q 4                          // queries per warp
#define BQ_WPB 4                        // warps per block
#define BQ_THREADS (BQ_WPB * 32)        // 128
#define BQ_QPB (BQ_WPB * BQ_Q)          // 16 queries per block
#define BQ_BPB (BQ_N / BQ_QPB)          // 128 blocks per batch
#define BQ_TILE 512
#define BQ_R2 0.04f

__global__ __launch_bounds__(BQ_THREADS, 10)
void SelfBallPointQuery_56736517980692_kernel(const float* __restrict__ pcs,
                                              float* __restrict__ out) {
    __shared__ float4 pts[BQ_TILE];     // 8 KB tile

    const int b   = blockIdx.x / BQ_BPB;
    const int blk = blockIdx.x % BQ_BPB;
    const float* base = pcs + (size_t)b * 3 * BQ_N;   // [c][n]: x,+N y,+2N z

    const int warp = threadIdx.x >> 5;
    const int lane = threadIdx.x & 31;
    const unsigned below = (1u << lane) - 1u;
    const int i0 = blk * BQ_QPB + warp * BQ_Q;        // this warp's 4 queries

    float qx[BQ_Q], qy[BQ_Q], qz[BQ_Q];
    int cnt[BQ_Q];
#pragma unroll
    for (int q = 0; q < BQ_Q; ++q) {
        qx[q] = base[i0 + q];
        qy[q] = base[BQ_N + i0 + q];
        qz[q] = base[2 * BQ_N + i0 + q];
        cnt[q] = 0;
    }
    float* row0 = out + (size_t)(b * BQ_N + i0) * BQ_MS;

    float jf = (float)lane;             // float(j) for this lane, exact
    for (int t = 0; t < BQ_N; t += BQ_TILE) {
        __syncthreads();                // protect smem reuse across tiles
        for (int n = threadIdx.x; n < BQ_TILE; n += BQ_THREADS) {
            const int g = t + n;
            pts[n] = make_float4(base[g], base[BQ_N + g], base[2 * BQ_N + g], 0.0f);
        }
        __syncthreads();

#pragma unroll 4
        for (int jb = 0; jb < BQ_TILE; jb += 32) {
            const float4 p = pts[jb + lane];    // conflict-free LDS.128
#pragma unroll
            for (int q = 0; q < BQ_Q; ++q) {
                const float dx = qx[q] - p.x;
                const float dy = qy[q] - p.y;
                const float dz = qz[q] - p.z;
                float acc = __fmul_rn(dx, dx);          // EXACT form: benched
                acc = __fmaf_rn(dy, dy, acc);           // rel_err 0.0
                acc = __fmaf_rn(dz, dz, acc);
                const bool hit = acc < BQ_R2;
                const unsigned m = __ballot_sync(0xffffffffu, hit);
                const int pos = cnt[q] + __popc(m & below);
                if (hit && pos < BQ_MS) row0[(q << 6) + pos] = jf;  // rare pred STG
                cnt[q] += __popc(m);
            }
            jf += 32.0f;
        }
    }

    // Padding: slot 0 always holds the first in-radius index (self guarantees
    // a hit whose compacted position is 0). __syncwarp orders the store.
    __syncwarp();
#pragma unroll
    for (int q = 0; q < BQ_Q; ++q) {
        const int start = cnt[q] < BQ_MS ? cnt[q] : BQ_MS;   // warp-uniform
        if (start < BQ_MS) {
            const float f = row0[q << 6];
            for (int k = start + lane; k < BQ_MS; k += 32) {
                row0[(q << 6) + k] = f;
            }
        }
    }
}

extern "C" void kernel_launch(void* const* d_in, const int* in_sizes, int n_in,
                              void* d_out, int out_size) {
    (void)in_sizes; (void)n_in; (void)out_size;
    const float* pcs = (const float*)d_in[0];
    float*       out = (float*)d_out;
    dim3 grid(BQ_B * BQ_BPB);   // 2048 blocks
    dim3 block(BQ_THREADS);     // 128 threads
    SelfBallPointQuery_56736517980692_kernel<<<grid, block>>>(pcs, out);
}

// round 12
// speedup vs baseline: 4.7126x; 1.0907x over previous
#include <cuda_runtime.h>
#include <cuda_bf16.h>

// SelfBallPointQuery: B=16, C=3, N=2048, RADIUS=0.2, MAX_SAMPLES=64
// Output float32 (B, N, 64): first 64 ascending in-radius indices, padded
// with the first in-radius index.
//
// R12 over R11 (49.7us, occ 47%, issue 78%): packed f32x2 math. Each lane
// evaluates TWO points per instruction via add/mul/fma.rn.f32x2 (sm_100+
// packed pairs; each half independently rounded -> membership predicate is
// bit-identical to the scalar exact form that benched rel_err 0.0).
// SMEM is coordinate-split into 64-bit (j, j+32) pairs, pre-negated so
// dx = q + (-p) == q - p exactly. Ballot lo before hi keeps ascending order.

#define BQ_B 16
#define BQ_N 2048
#define BQ_MS 64
#define BQ_Q 4                          // queries per warp
#define BQ_WPB 4                        // warps per block
#define BQ_THREADS (BQ_WPB * 32)        // 128
#define BQ_QPB (BQ_WPB * BQ_Q)          // 16 queries per block
#define BQ_BPB (BQ_N / BQ_QPB)          // 128 blocks per batch
#define BQ_R2 0.04f
#define BQ_GROUPS (BQ_N / 64)           // 32 groups of 64 points
#define BQ_SLOTS (BQ_GROUPS * 32)       // 1024 pair-slots per coord

#define ADD2(d, a, b) asm("add.rn.f32x2 %0, %1, %2;" : "=l"(d) : "l"(a), "l"(b))
#define MUL2(d, a, b) asm("mul.rn.f32x2 %0, %1, %2;" : "=l"(d) : "l"(a), "l"(b))
#define FMA2(d, a, b, c) asm("fma.rn.f32x2 %0, %1, %2, %3;" : "=l"(d) : "l"(a), "l"(b), "l"(c))
#define UNPK(lo, hi, a) asm("mov.b64 {%0, %1}, %2;" : "=f"(lo), "=f"(hi) : "l"(a))

__global__ __launch_bounds__(BQ_THREADS, 8)
void SelfBallPointQuery_56736517980692_kernel(const float* __restrict__ pcs,
                                              float* __restrict__ out) {
    // Coord-split pair layout: slot (g*32+l) holds (coord[g*64+l], coord[g*64+32+l]),
    // both NEGATED. 3 x 8 KB = 24 KB.
    __shared__ unsigned long long sx[BQ_SLOTS], sy[BQ_SLOTS], sz[BQ_SLOTS];

    const int b   = blockIdx.x / BQ_BPB;
    const int blk = blockIdx.x % BQ_BPB;
    const float* base = pcs + (size_t)b * 3 * BQ_N;   // [c][n]: x,+N y,+2N z

    {
        float* fx = (float*)sx; float* fy = (float*)sy; float* fz = (float*)sz;
        for (int n = threadIdx.x; n < BQ_N; n += BQ_THREADS) {
            const int g = n >> 6, r = n & 63, half = r >> 5, l = r & 31;
            const int e = ((g << 5) | l) * 2 + half;
            fx[e] = -base[n];
            fy[e] = -base[BQ_N + n];
            fz[e] = -base[2 * BQ_N + n];
        }
    }
    __syncthreads();

    const int warp = threadIdx.x >> 5;
    const int lane = threadIdx.x & 31;
    const unsigned below = (1u << lane) - 1u;
    const int i0 = blk * BQ_QPB + warp * BQ_Q;        // this warp's 4 queries

    unsigned long long qxp[BQ_Q], qyp[BQ_Q], qzp[BQ_Q];
    int cnt[BQ_Q];
#pragma unroll
    for (int q = 0; q < BQ_Q; ++q) {
        const float x = base[i0 + q];
        const float y = base[BQ_N + i0 + q];
        const float z = base[2 * BQ_N + i0 + q];
        asm("mov.b64 %0, {%1, %1};" : "=l"(qxp[q]) : "f"(x));
        asm("mov.b64 %0, {%1, %1};" : "=l"(qyp[q]) : "f"(y));
        asm("mov.b64 %0, {%1, %1};" : "=l"(qzp[q]) : "f"(z));
        cnt[q] = 0;
    }
    float* row0 = out + (size_t)(b * BQ_N + i0) * BQ_MS;

    float jf_lo = (float)lane;          // j for low half of this lane's pair
    float jf_hi = (float)(lane + 32);   // j for high half

#pragma unroll 2
    for (int g = 0; g < BQ_GROUPS; ++g) {
        const int s = (g << 5) + lane;
        const unsigned long long px = sx[s];   // LDS.64, conflict-free
        const unsigned long long py = sy[s];
        const unsigned long long pz = sz[s];

#pragma unroll
        for (int q = 0; q < BQ_Q; ++q) {
            unsigned long long dx, dy, dz, acc;
            ADD2(dx, qxp[q], px);              // q + (-p) == q - p, bit-exact
            ADD2(dy, qyp[q], py);
            ADD2(dz, qzp[q], pz);
            MUL2(acc, dx, dx);                 // r(dx*dx)
            FMA2(acc, dy, dy, acc);            // fma(dy,dy,acc)
            FMA2(acc, dz, dz, acc);            // fma(dz,dz,acc)
            float alo, ahi;
            UNPK(alo, ahi, acc);

            const bool hlo = alo < BQ_R2;
            const bool hhi = ahi < BQ_R2;
            const unsigned mlo = __ballot_sync(0xffffffffu, hlo);
            const unsigned mhi = __ballot_sync(0xffffffffu, hhi);

            const int plo = cnt[q] + __popc(mlo & below);
            if (hlo && plo < BQ_MS) row0[(q << 6) + plo] = jf_lo;
            const int mid = cnt[q] + __popc(mlo);
            const int phi = mid + __popc(mhi & below);
            if (hhi && phi < BQ_MS) row0[(q << 6) + phi] = jf_hi;
            cnt[q] = mid + __popc(mhi);
        }
        jf_lo += 64.0f;
        jf_hi += 64.0f;
    }

    // Padding: slot 0 always holds the first in-radius index (self always
    // hits; its compacted position is 0). __syncwarp orders that store.
    __syncwarp();
#pragma unroll
    for (int q = 0; q < BQ_Q; ++q) {
        const int start = cnt[q] < BQ_MS ? cnt[q] : BQ_MS;   // warp-uniform
        if (start < BQ_MS) {
            const float f = row0[q << 6];
            for (int k = start + lane; k < BQ_MS; k += 32) {
                row0[(q << 6) + k] = f;
            }
        }
    }
}

extern "C" void kernel_launch(void* const* d_in, const int* in_sizes, int n_in,
                              void* d_out, int out_size) {
    (void)in_sizes; (void)n_in; (void)out_size;
    const float* pcs = (const float*)d_in[0];
    float*       out = (float*)d_out;
    dim3 grid(BQ_B * BQ_BPB);   // 2048 blocks
    dim3 block(BQ_THREADS);     // 128 threads
    SelfBallPointQuery_56736517980692_kernel<<<grid, block>>>(pcs, out);
}